// round 1
// baseline (speedup 1.0000x reference)
#include <cuda_runtime.h>
#include <cstdint>

#define Bsz 256
#define Dd  256
#define Tt  512
#define Hh  512
#define G4  2048

// ---------------- scratch (device globals; no allocs allowed) ----------------
__device__ float g_xg[(size_t)Tt * Bsz * G4];   // [t][b][g]   1 GB
__device__ float g_WT[(size_t)Hh * G4];         // [k][j]      W_hh transposed
__device__ float g_hA[Bsz * Hh];
__device__ float g_hB[Bsz * Hh];
__device__ float g_c [Bsz * Hh];
__device__ float g_part[(size_t)Tt * Bsz * 16]; // per-(t,b) partial logits, 16 n-tiles

// ---------------- f32x2 helpers ----------------
__device__ __forceinline__ unsigned long long pk2(float lo, float hi) {
    unsigned long long r;
    asm("mov.b64 %0, {%1,%2};" : "=l"(r) : "f"(lo), "f"(hi));
    return r;
}
__device__ __forceinline__ void upk2(unsigned long long v, float& lo, float& hi) {
    asm("mov.b64 {%0,%1}, %2;" : "=f"(lo), "=f"(hi) : "l"(v));
}
__device__ __forceinline__ unsigned long long ffma2(unsigned long long a,
                                                    unsigned long long b,
                                                    unsigned long long c) {
    unsigned long long d;
    asm("fma.rn.f32x2 %0, %1, %2, %3;" : "=l"(d) : "l"(a), "l"(b), "l"(c));
    return d;
}

__device__ __forceinline__ float sigf(float x) {
    return 1.0f / (1.0f + __expf(-x));
}
__device__ __forceinline__ float tanhf_fast(float x) {
    // exact at saturation: exp(2x)->inf => 1, exp(2x)->0 => -1
    return 1.0f - 2.0f / (__expf(2.0f * x) + 1.0f);
}

// ---------------- init: zero h0 and c0 ----------------
__global__ void init_state() {
    int idx = blockIdx.x * blockDim.x + threadIdx.x;   // 512*256 = 131072 threads
    if (idx < Bsz * Hh) {
        g_hA[idx] = 0.0f;
        g_c[idx]  = 0.0f;
    }
}

// ---------------- transpose W_hh -> g_WT[k][j] ----------------
__global__ void transpose_whh(const float* __restrict__ Whh) {
    __shared__ float tile[32][33];
    int j0 = blockIdx.x * 32;   // over 2048
    int k0 = blockIdx.y * 32;   // over 512
    int tx = threadIdx.x, ty = threadIdx.y;  // 32 x 8
#pragma unroll
    for (int r = 0; r < 4; r++)
        tile[ty + r * 8][tx] = Whh[(size_t)(j0 + ty + r * 8) * Hh + k0 + tx];
    __syncthreads();
#pragma unroll
    for (int r = 0; r < 4; r++)
        g_WT[(size_t)(k0 + ty + r * 8) * G4 + j0 + tx] = tile[tx][ty + r * 8];
}

// ---------------- precompute x_gates: per-b GEMM (T x D) @ (D x 4H) ----------------
// block tile: 64 t x 128 g, K = 256, 256 threads, micro 4t x 8g via f32x2.
__global__ void __launch_bounds__(256) xgate_gemm(const float* __restrict__ x,
                                                  const float* __restrict__ Wih,
                                                  const float* __restrict__ bih,
                                                  const float* __restrict__ bhh) {
    __shared__ float A_s[16][64];    // [d][t]
    __shared__ float B_s[16][128];   // [d][g]
    const int tid = threadIdx.x;
    const int g0 = blockIdx.x * 128;
    const int t0 = blockIdx.y * 64;
    const int b  = blockIdx.z;
    const int ti = tid & 15;         // 4 t per thread
    const int gi = tid >> 4;         // 8 g per thread

    unsigned long long acc[4][4];
#pragma unroll
    for (int i = 0; i < 4; i++)
#pragma unroll
        for (int p = 0; p < 4; p++) acc[i][p] = 0ULL;

    const float* xb = x + (size_t)b * Dd * Tt;

    for (int d0 = 0; d0 < Dd; d0 += 16) {
        __syncthreads();
        {   // stage A: 16 d x 64 t (coalesced along t)
            int tt = tid & 63, dd = tid >> 6;   // dd 0..3
#pragma unroll
            for (int r = 0; r < 4; r++)
                A_s[dd + r * 4][tt] = xb[(size_t)(d0 + dd + r * 4) * Tt + t0 + tt];
        }
        {   // stage B: 16 d x 128 g (coalesced along d)
            int gg = tid >> 1, half = tid & 1;
            const float* wsrc = Wih + (size_t)(g0 + gg) * Dd + d0 + half * 8;
            float4 v0 = *(const float4*)(wsrc);
            float4 v1 = *(const float4*)(wsrc + 4);
            int dd = half * 8;
            B_s[dd + 0][gg] = v0.x; B_s[dd + 1][gg] = v0.y;
            B_s[dd + 2][gg] = v0.z; B_s[dd + 3][gg] = v0.w;
            B_s[dd + 4][gg] = v1.x; B_s[dd + 5][gg] = v1.y;
            B_s[dd + 6][gg] = v1.z; B_s[dd + 7][gg] = v1.w;
        }
        __syncthreads();
#pragma unroll
        for (int dd = 0; dd < 16; dd++) {
            float4 a = *(const float4*)&A_s[dd][ti * 4];
            unsigned long long ap0 = pk2(a.x, a.x);
            unsigned long long ap1 = pk2(a.y, a.y);
            unsigned long long ap2 = pk2(a.z, a.z);
            unsigned long long ap3 = pk2(a.w, a.w);
            const unsigned long long* bp = (const unsigned long long*)&B_s[dd][gi * 8];
            unsigned long long b0 = bp[0], b1 = bp[1], b2 = bp[2], b3 = bp[3];
            acc[0][0] = ffma2(ap0, b0, acc[0][0]); acc[0][1] = ffma2(ap0, b1, acc[0][1]);
            acc[0][2] = ffma2(ap0, b2, acc[0][2]); acc[0][3] = ffma2(ap0, b3, acc[0][3]);
            acc[1][0] = ffma2(ap1, b0, acc[1][0]); acc[1][1] = ffma2(ap1, b1, acc[1][1]);
            acc[1][2] = ffma2(ap1, b2, acc[1][2]); acc[1][3] = ffma2(ap1, b3, acc[1][3]);
            acc[2][0] = ffma2(ap2, b0, acc[2][0]); acc[2][1] = ffma2(ap2, b1, acc[2][1]);
            acc[2][2] = ffma2(ap2, b2, acc[2][2]); acc[2][3] = ffma2(ap2, b3, acc[2][3]);
            acc[3][0] = ffma2(ap3, b0, acc[3][0]); acc[3][1] = ffma2(ap3, b1, acc[3][1]);
            acc[3][2] = ffma2(ap3, b2, acc[3][2]); acc[3][3] = ffma2(ap3, b3, acc[3][3]);
        }
    }

    // epilogue: + (b_ih + b_hh), store [t][b][g]
    float bias[8];
#pragma unroll
    for (int j = 0; j < 8; j++)
        bias[j] = bih[g0 + gi * 8 + j] + bhh[g0 + gi * 8 + j];

#pragma unroll
    for (int it = 0; it < 4; it++) {
        int tt = t0 + ti * 4 + it;
        float v[8];
#pragma unroll
        for (int p = 0; p < 4; p++) upk2(acc[it][p], v[2 * p], v[2 * p + 1]);
#pragma unroll
        for (int j = 0; j < 8; j++) v[j] += bias[j];
        float* dst = g_xg + ((size_t)tt * Bsz + b) * G4 + g0 + gi * 8;
        *(float4*)(dst)     = make_float4(v[0], v[1], v[2], v[3]);
        *(float4*)(dst + 4) = make_float4(v[4], v[5], v[6], v[7]);
    }
}

// ---------------- one LSTM timestep ----------------
// grid 128 = (8 b-tiles x 16 n-tiles), 256 threads.
// block: 32 b x 32 n, computing all 4 gates for its n's (4*32 = 128 W rows), K = 512.
// thread: warp w -> 4 batches b0+w*4+{0..3}; lane l -> hidden unit n0+l.
__global__ void __launch_bounds__(256) lstm_step(const float* __restrict__ Wmlp, int t) {
    __shared__ float2 h_s2[16][64];   // [b-pair][k]  pre-packed pairs, 8 KB
    __shared__ float  w_s[64][128];   // [k][gate*32+l], 32 KB

    const float* hprev = (t & 1) ? g_hB : g_hA;
    float*       hnext = (t & 1) ? g_hA : g_hB;

    const int tid = threadIdx.x;
    const int w = tid >> 5, l = tid & 31;
    const int bb = blockIdx.x & 7, nn = blockIdx.x >> 3;
    const int b0 = bb * 32, n0 = nn * 32;
    const int bq = b0 + w * 4;

    unsigned long long acc[2][4];
#pragma unroll
    for (int p = 0; p < 2; p++)
#pragma unroll
        for (int g = 0; g < 4; g++) acc[p][g] = 0ULL;

    for (int kc = 0; kc < Hh; kc += 64) {
        __syncthreads();
        {   // stage h chunk, pre-packed as (b, b+1) pairs
            int bL = tid >> 3;             // 0..31
            int kL = (tid & 7) * 8;        // 0,8,...,56
            const float* src = hprev + (size_t)(b0 + bL) * Hh + kc + kL;
            float4 v0 = *(const float4*)(src);
            float4 v1 = *(const float4*)(src + 4);
            float* hs = (float*)h_s2;      // layout [pair][k][2]
            int base = (bL >> 1) * 128 + (bL & 1);
            hs[base + (kL + 0) * 2] = v0.x; hs[base + (kL + 1) * 2] = v0.y;
            hs[base + (kL + 2) * 2] = v0.z; hs[base + (kL + 3) * 2] = v0.w;
            hs[base + (kL + 4) * 2] = v1.x; hs[base + (kL + 5) * 2] = v1.y;
            hs[base + (kL + 6) * 2] = v1.z; hs[base + (kL + 7) * 2] = v1.w;
        }
        {   // stage W chunk: 64 k x (4 gates x 32 n)
#pragma unroll
            for (int r = 0; r < 32; r++) {
                int idx = tid + r * 256;         // 0..8191
                int k = idx >> 7, j = idx & 127;
                int g = j >> 5, ll = j & 31;
                w_s[k][j] = g_WT[(size_t)(kc + k) * G4 + g * Hh + n0 + ll];
            }
        }
        __syncthreads();
#pragma unroll 8
        for (int k = 0; k < 64; k++) {
            unsigned long long hp0 = *(const unsigned long long*)&h_s2[w * 2 + 0][k];
            unsigned long long hp1 = *(const unsigned long long*)&h_s2[w * 2 + 1][k];
#pragma unroll
            for (int g = 0; g < 4; g++) {
                float wv = w_s[k][g * 32 + l];
                unsigned long long wp = pk2(wv, wv);
                acc[0][g] = ffma2(hp0, wp, acc[0][g]);
                acc[1][g] = ffma2(hp1, wp, acc[1][g]);
            }
        }
    }

    const int n = n0 + l;
    float pre[4][4];    // [batch][gate]
#pragma unroll
    for (int g = 0; g < 4; g++) {
        upk2(acc[0][g], pre[0][g], pre[1][g]);
        upk2(acc[1][g], pre[2][g], pre[3][g]);
    }

    float wmlp_n = Wmlp[n];
    float psum[4];
#pragma unroll
    for (int i = 0; i < 4; i++) {
        int b = bq + i;
        const float* xg = g_xg + ((size_t)t * Bsz + b) * G4 + n;
        float gi = pre[i][0] + xg[0];
        float gf = pre[i][1] + xg[512];
        float gc = pre[i][2] + xg[1024];
        float go = pre[i][3] + xg[1536];
        float si = sigf(gi);
        float sf = sigf(gf);
        float tg = tanhf_fast(gc);
        float so = sigf(go);
        int ci = b * Hh + n;
        float c_new = sf * g_c[ci] + si * tg;
        g_c[ci] = c_new;
        float h_new = so * tanhf_fast(c_new);
        hnext[ci] = h_new;
        psum[i] = h_new * wmlp_n;
    }
    // warp-reduce partial logits over the 32 n's of this tile
#pragma unroll
    for (int off = 16; off; off >>= 1) {
#pragma unroll
        for (int i = 0; i < 4; i++)
            psum[i] += __shfl_xor_sync(0xffffffffu, psum[i], off);
    }
    if (l == 0) {
#pragma unroll
        for (int i = 0; i < 4; i++) {
            int b = bq + i;
            g_part[((size_t)t * Bsz + b) * 16 + nn] = psum[i];
        }
    }
}

// ---------------- finalize: sum 16 partials, + b_mlp, sigmoid ----------------
__global__ void finalize(const float* __restrict__ bmlp, float* __restrict__ out) {
    int idx = blockIdx.x * blockDim.x + threadIdx.x;   // t*256 + b
    if (idx >= Tt * Bsz) return;
    int t = idx >> 8, b = idx & 255;
    const float4* p = (const float4*)(g_part + (size_t)idx * 16);
    float4 a = p[0], c = p[1], d = p[2], e = p[3];
    float s = ((a.x + a.y) + (a.z + a.w)) + ((c.x + c.y) + (c.z + c.w))
            + ((d.x + d.y) + (d.z + d.w)) + ((e.x + e.y) + (e.z + e.w))
            + bmlp[0];
    out[(size_t)b * Tt + t] = 1.0f / (1.0f + __expf(-s));
}

// ---------------- launch ----------------
extern "C" void kernel_launch(void* const* d_in, const int* in_sizes, int n_in,
                              void* d_out, int out_size) {
    const float* x    = (const float*)d_in[0];
    const float* Wih  = (const float*)d_in[1];
    const float* Whh  = (const float*)d_in[2];
    const float* bih  = (const float*)d_in[3];
    const float* bhh  = (const float*)d_in[4];
    const float* Wmlp = (const float*)d_in[5];
    const float* bmlp = (const float*)d_in[6];
    float* out = (float*)d_out;

    init_state<<<512, 256>>>();
    transpose_whh<<<dim3(G4 / 32, Hh / 32), dim3(32, 8)>>>(Whh);
    xgate_gemm<<<dim3(G4 / 128, Tt / 64, Bsz), 256>>>(x, Wih, bih, bhh);
    for (int t = 0; t < Tt; t++)
        lstm_step<<<128, 256>>>(Wmlp, t);
    finalize<<<512, 256>>>(bmlp, out);
}

// round 3
// speedup vs baseline: 1.5008x; 1.5008x over previous
#include <cuda_runtime.h>
#include <cstdint>

#define Bsz 256
#define Dd  256
#define Tt  512
#define Hh  512
#define G4  2048
#define NBLK 128

// ---------------- scratch (device globals; no allocs allowed) ----------------
__device__ float g_xg[(size_t)Tt * Bsz * G4];   // [t][b][j]  1 GB
__device__ float g_hA[Hh * Bsz];                // h ping-pong, [n][b] layout
__device__ float g_hB[Hh * Bsz];
__device__ float g_part[(size_t)Tt * Bsz * 32]; // per-(t,b) partial logits, 32 n-tiles
__device__ unsigned g_cnt;                      // grid barrier counter

// ---------------- f32x2 helpers ----------------
typedef unsigned long long ull;
__device__ __forceinline__ ull pk2(float lo, float hi) {
    ull r;
    asm("mov.b64 %0, {%1,%2};" : "=l"(r) : "f"(lo), "f"(hi));
    return r;
}
__device__ __forceinline__ void upk2(ull v, float& lo, float& hi) {
    asm("mov.b64 {%0,%1}, %2;" : "=f"(lo), "=f"(hi) : "l"(v));
}
__device__ __forceinline__ ull ffma2(ull a, ull b, ull c) {
    ull d;
    asm("fma.rn.f32x2 %0, %1, %2, %3;" : "=l"(d) : "l"(a), "l"(b), "l"(c));
    return d;
}

__device__ __forceinline__ float sigf(float x) {
    return 1.0f / (1.0f + __expf(-x));
}
__device__ __forceinline__ float tanhf_fast(float x) {
    return 1.0f - 2.0f / (__expf(2.0f * x) + 1.0f);
}

// ---------------- init: zero h0 and barrier counter ----------------
__global__ void init_state() {
    int idx = blockIdx.x * blockDim.x + threadIdx.x;   // 131072 threads
    if (idx < Hh * Bsz) g_hA[idx] = 0.0f;
    if (idx == 0) g_cnt = 0u;
}

// ---------------- precompute x_gates: per-b GEMM (T x D) @ (D x 4H) ----------------
__global__ void __launch_bounds__(256) xgate_gemm(const float* __restrict__ x,
                                                  const float* __restrict__ Wih,
                                                  const float* __restrict__ bih,
                                                  const float* __restrict__ bhh) {
    __shared__ float A_s[16][64];    // [d][t]
    __shared__ float B_s[16][128];   // [d][g]
    const int tid = threadIdx.x;
    const int g0 = blockIdx.x * 128;
    const int t0 = blockIdx.y * 64;
    const int b  = blockIdx.z;
    const int ti = tid & 15;
    const int gi = tid >> 4;

    ull acc[4][4];
#pragma unroll
    for (int i = 0; i < 4; i++)
#pragma unroll
        for (int p = 0; p < 4; p++) acc[i][p] = 0ULL;

    const float* xb = x + (size_t)b * Dd * Tt;

    for (int d0 = 0; d0 < Dd; d0 += 16) {
        __syncthreads();
        {
            int tt = tid & 63, dd = tid >> 6;
#pragma unroll
            for (int r = 0; r < 4; r++)
                A_s[dd + r * 4][tt] = xb[(size_t)(d0 + dd + r * 4) * Tt + t0 + tt];
        }
        {
            int gg = tid >> 1, half = tid & 1;
            const float* wsrc = Wih + (size_t)(g0 + gg) * Dd + d0 + half * 8;
            float4 v0 = *(const float4*)(wsrc);
            float4 v1 = *(const float4*)(wsrc + 4);
            int dd = half * 8;
            B_s[dd + 0][gg] = v0.x; B_s[dd + 1][gg] = v0.y;
            B_s[dd + 2][gg] = v0.z; B_s[dd + 3][gg] = v0.w;
            B_s[dd + 4][gg] = v1.x; B_s[dd + 5][gg] = v1.y;
            B_s[dd + 6][gg] = v1.z; B_s[dd + 7][gg] = v1.w;
        }
        __syncthreads();
#pragma unroll
        for (int dd = 0; dd < 16; dd++) {
            float4 a = *(const float4*)&A_s[dd][ti * 4];
            ull ap0 = pk2(a.x, a.x);
            ull ap1 = pk2(a.y, a.y);
            ull ap2 = pk2(a.z, a.z);
            ull ap3 = pk2(a.w, a.w);
            const ull* bp = (const ull*)&B_s[dd][gi * 8];
            ull b0 = bp[0], b1 = bp[1], b2 = bp[2], b3 = bp[3];
            acc[0][0] = ffma2(ap0, b0, acc[0][0]); acc[0][1] = ffma2(ap0, b1, acc[0][1]);
            acc[0][2] = ffma2(ap0, b2, acc[0][2]); acc[0][3] = ffma2(ap0, b3, acc[0][3]);
            acc[1][0] = ffma2(ap1, b0, acc[1][0]); acc[1][1] = ffma2(ap1, b1, acc[1][1]);
            acc[1][2] = ffma2(ap1, b2, acc[1][2]); acc[1][3] = ffma2(ap1, b3, acc[1][3]);
            acc[2][0] = ffma2(ap2, b0, acc[2][0]); acc[2][1] = ffma2(ap2, b1, acc[2][1]);
            acc[2][2] = ffma2(ap2, b2, acc[2][2]); acc[2][3] = ffma2(ap2, b3, acc[2][3]);
            acc[3][0] = ffma2(ap3, b0, acc[3][0]); acc[3][1] = ffma2(ap3, b1, acc[3][1]);
            acc[3][2] = ffma2(ap3, b2, acc[3][2]); acc[3][3] = ffma2(ap3, b3, acc[3][3]);
        }
    }

    float bias[8];
#pragma unroll
    for (int j = 0; j < 8; j++)
        bias[j] = bih[g0 + gi * 8 + j] + bhh[g0 + gi * 8 + j];

#pragma unroll
    for (int it = 0; it < 4; it++) {
        int tt = t0 + ti * 4 + it;
        float v[8];
#pragma unroll
        for (int p = 0; p < 4; p++) upk2(acc[it][p], v[2 * p], v[2 * p + 1]);
#pragma unroll
        for (int j = 0; j < 8; j++) v[j] += bias[j];
        float* dst = g_xg + ((size_t)tt * Bsz + b) * G4 + g0 + gi * 8;
        *(float4*)(dst)     = make_float4(v[0], v[1], v[2], v[3]);
        *(float4*)(dst + 4) = make_float4(v[4], v[5], v[6], v[7]);
    }
}

// ---------------- persistent LSTM: all 512 steps, grid barrier per step ----------------
// 128 blocks x 256 threads. block = (b-tile 64) x (n-tile 16 -> 64 j with 4 gates).
// W tile (512 k x 64 j = 128 KB) resident in SMEM for the whole kernel.
// c tile (64 x 16) resident in SMEM. h ping-pongs through global in [n][b] layout.
// thread: nl = tid&15 (one n), bq = tid>>4 (4 batches). 8 f32x2 accumulators.
__global__ void __launch_bounds__(256) lstm_persist(const float* __restrict__ Whh,
                                                    const float* __restrict__ Wmlp) {
    extern __shared__ float sm[];
    float* ws = sm;                    // [512][64]  j = nl*4 + gate
    float* hs = sm + 512 * 64;         // [2][32][64]  double-buffered h chunk [k][b]
    float* cs = hs + 2 * 32 * 64;      // [64][16]

    const int tid = threadIdx.x;
    const int nl  = tid & 15;
    const int bq  = tid >> 4;          // 0..15
    const int b0  = (blockIdx.x >> 5) * 64;
    const int n0  = (blockIdx.x & 31) * 16;
    const int n   = n0 + nl;
    const int ntile = blockIdx.x & 31;

    // One-time: stage W tile (coalesced along k), zero c tile.
    for (int idx = tid; idx < 64 * 512; idx += 256) {
        int k = idx & 511, c = idx >> 9;          // c = nl2*4 + g
        ws[k * 64 + c] = Whh[(size_t)((c & 3) * Hh + n0 + (c >> 2)) * Hh + k];
    }
    for (int idx = tid; idx < 1024; idx += 256) cs[idx] = 0.0f;
    const float wm = Wmlp[n];
    __syncthreads();

    const int kk0 = tid >> 3;          // 0..31 (chunk row)
    const int bb8 = (tid & 7) * 8;     // 8 floats per thread per chunk row

    for (int t = 0; t < Tt; ++t) {
        const float* hprev = (t & 1) ? g_hB : g_hA;
        float*       hnext = (t & 1) ? g_hA : g_hB;

        // Prefetch this thread's 16 x_gate values (streaming; hidden under GEMM).
        float xr[16];
        {
            const float* xb = g_xg + ((size_t)t * Bsz + b0 + bq * 4) * G4 + n;
#pragma unroll
            for (int i = 0; i < 4; ++i)
#pragma unroll
                for (int g = 0; g < 4; ++g)
                    xr[i * 4 + g] = __ldcs(xb + (size_t)i * G4 + g * Hh);
        }

        ull acc[4][2];
#pragma unroll
        for (int i = 0; i < 4; ++i) { acc[i][0] = 0ULL; acc[i][1] = 0ULL; }

        // Preload h chunk 0 (L2-only loads: stale-L1 safe)
        float4 r0 = __ldcg((const float4*)(hprev + (size_t)kk0 * Bsz + b0 + bb8));
        float4 r1 = __ldcg((const float4*)(hprev + (size_t)kk0 * Bsz + b0 + bb8 + 4));
        int buf = 0;

        for (int ch = 0; ch < 16; ++ch) {
            float* hdst = hs + (buf * 32 + kk0) * 64 + bb8;
            *(float4*)(hdst)     = r0;
            *(float4*)(hdst + 4) = r1;
            if (ch < 15) {
                const float* src = hprev + (size_t)((ch + 1) * 32 + kk0) * Bsz + b0 + bb8;
                r0 = __ldcg((const float4*)(src));
                r1 = __ldcg((const float4*)(src + 4));
            }
            __syncthreads();

            const float* hrow = hs + buf * 2048;
            const float* wrow = ws + ch * 32 * 64;
#pragma unroll 8
            for (int k = 0; k < 32; ++k) {
                ulonglong2 wp = *(const ulonglong2*)(wrow + k * 64 + nl * 4); // (gi,gf),(gg,go)
                float4 hv = *(const float4*)(hrow + k * 64 + bq * 4);
                ull hd0 = pk2(hv.x, hv.x);
                ull hd1 = pk2(hv.y, hv.y);
                ull hd2 = pk2(hv.z, hv.z);
                ull hd3 = pk2(hv.w, hv.w);
                acc[0][0] = ffma2(hd0, wp.x, acc[0][0]); acc[0][1] = ffma2(hd0, wp.y, acc[0][1]);
                acc[1][0] = ffma2(hd1, wp.x, acc[1][0]); acc[1][1] = ffma2(hd1, wp.y, acc[1][1]);
                acc[2][0] = ffma2(hd2, wp.x, acc[2][0]); acc[2][1] = ffma2(hd2, wp.y, acc[2][1]);
                acc[3][0] = ffma2(hd3, wp.x, acc[3][0]); acc[3][1] = ffma2(hd3, wp.y, acc[3][1]);
            }
            buf ^= 1;
        }

        // Activation + state update + MLP partial (all thread-local).
        float ps[4];
#pragma unroll
        for (int i = 0; i < 4; ++i) {
            int bl = bq * 4 + i;
            float pi, pf, pg, po;
            upk2(acc[i][0], pi, pf);
            upk2(acc[i][1], pg, po);
            float gi = sigf(pi + xr[i * 4 + 0]);
            float gf = sigf(pf + xr[i * 4 + 1]);
            float gg = tanhf_fast(pg + xr[i * 4 + 2]);
            float go = sigf(po + xr[i * 4 + 3]);
            float cn = gf * cs[bl * 16 + nl] + gi * gg;
            cs[bl * 16 + nl] = cn;
            float hn = go * tanhf_fast(cn);
            __stcg(hnext + (size_t)n * Bsz + b0 + bl, hn);
            ps[i] = hn * wm;
        }
#pragma unroll
        for (int off = 8; off; off >>= 1)
#pragma unroll
            for (int i = 0; i < 4; ++i)
                ps[i] += __shfl_xor_sync(0xffffffffu, ps[i], off);
        if (nl == 0) {
#pragma unroll
            for (int i = 0; i < 4; ++i)
                g_part[((size_t)t * Bsz + b0 + bq * 4 + i) * 32 + ntile] = ps[i];
        }

        // ---- grid barrier (monotonic counter; all 128 blocks resident) ----
        __threadfence();
        __syncthreads();
        if (tid == 0) {
            unsigned tgt = (unsigned)(t + 1) * NBLK;
            atomicAdd(&g_cnt, 1u);
            while (*((volatile unsigned*)&g_cnt) < tgt) { }
            __threadfence();
        }
        __syncthreads();
    }
}

// ---------------- finalize: sum 32 partials, + b_mlp, sigmoid ----------------
__global__ void finalize(const float* __restrict__ bmlp, float* __restrict__ out) {
    int idx = blockIdx.x * blockDim.x + threadIdx.x;   // t*256 + b
    if (idx >= Tt * Bsz) return;
    int t = idx >> 8, b = idx & 255;
    const float4* p = (const float4*)(g_part + (size_t)idx * 32);
    float s = bmlp[0];
#pragma unroll
    for (int q = 0; q < 8; q++) {
        float4 v = p[q];
        s += (v.x + v.y) + (v.z + v.w);
    }
    out[(size_t)b * Tt + t] = 1.0f / (1.0f + __expf(-s));
}

// ---------------- launch ----------------
extern "C" void kernel_launch(void* const* d_in, const int* in_sizes, int n_in,
                              void* d_out, int out_size) {
    const float* x    = (const float*)d_in[0];
    const float* Wih  = (const float*)d_in[1];
    const float* Whh  = (const float*)d_in[2];
    const float* bih  = (const float*)d_in[3];
    const float* bhh  = (const float*)d_in[4];
    const float* Wmlp = (const float*)d_in[5];
    const float* bmlp = (const float*)d_in[6];
    float* out = (float*)d_out;

    const int smem_bytes = (512 * 64 + 2 * 32 * 64 + 64 * 16) * 4;  // 151552
    cudaFuncSetAttribute(lstm_persist, cudaFuncAttributeMaxDynamicSharedMemorySize,
                         smem_bytes);

    init_state<<<512, 256>>>();
    xgate_gemm<<<dim3(G4 / 128, Tt / 64, Bsz), 256>>>(x, Wih, bih, bhh);
    lstm_persist<<<NBLK, 256, smem_bytes>>>(Whh, Wmlp);
    finalize<<<512, 256>>>(bmlp, out);
}

// round 5
// speedup vs baseline: 3.0781x; 2.0510x over previous
#include <cuda_runtime.h>
#include <cuda_bf16.h>
#include <cstdint>

#define Bsz 256
#define Dd  256
#define Tt  512
#define Hh  512
#define G4  2048
#define NBLK 128
#define PADK 520   // padded row length (bf16 elems) for ldmatrix bank spread

typedef unsigned long long ull;

// ---------------- scratch (device globals; no allocs allowed) ----------------
__device__ float g_xg[(size_t)Tt * Bsz * G4];          // [t][b][P] permuted, bias folded
__device__ __nv_bfloat16 g_hA[Bsz * Hh];               // h ping-pong, [b][k] bf16
__device__ __nv_bfloat16 g_hB[Bsz * Hh];
__device__ float g_part[(size_t)Tt * Bsz * 32];        // per-(t,b) partial logits
__device__ unsigned g_cnt;                             // grid barrier counter

// Permutation: storage col P  ->  original gate-row j = g*512 + U
// P = nt*64 + 32*a + 2*u + e   with  g = 2a+e,  U = nt*16 + u
__device__ __forceinline__ int orig_j(int P) {
    int nt = P >> 6, c = P & 63;
    int a = c >> 5, u = (c & 31) >> 1, e = c & 1;
    return (2 * a + e) * Hh + nt * 16 + u;
}

// ---------------- f32x2 helpers (xgate gemm) ----------------
__device__ __forceinline__ ull pk2(float lo, float hi) {
    ull r; asm("mov.b64 %0, {%1,%2};" : "=l"(r) : "f"(lo), "f"(hi)); return r;
}
__device__ __forceinline__ void upk2(ull v, float& lo, float& hi) {
    asm("mov.b64 {%0,%1}, %2;" : "=f"(lo), "=f"(hi) : "l"(v));
}
__device__ __forceinline__ ull ffma2(ull a, ull b, ull c) {
    ull d; asm("fma.rn.f32x2 %0, %1, %2, %3;" : "=l"(d) : "l"(a), "l"(b), "l"(c)); return d;
}
__device__ __forceinline__ float sigf(float x) { return 1.0f / (1.0f + __expf(-x)); }
__device__ __forceinline__ float tanhf_fast(float x) {
    return 1.0f - 2.0f / (__expf(2.0f * x) + 1.0f);
}

__device__ __forceinline__ uint32_t smem_u32(const void* p) {
    uint32_t a;
    asm("{ .reg .u64 t; cvta.to.shared.u64 t, %1; cvt.u32.u64 %0, t; }" : "=r"(a) : "l"(p));
    return a;
}

#define LDSM4(r0, r1, r2, r3, addr)                                               \
    asm volatile("ldmatrix.sync.aligned.m8n8.x4.shared.b16 {%0,%1,%2,%3}, [%4];"  \
                 : "=r"(r0), "=r"(r1), "=r"(r2), "=r"(r3) : "r"(addr))

#define MMA16816(d0, d1, d2, d3, a0, a1, a2, a3, b0, b1)                          \
    asm volatile("mma.sync.aligned.m16n8k16.row.col.f32.bf16.bf16.f32 "           \
                 "{%0,%1,%2,%3}, {%4,%5,%6,%7}, {%8,%9}, {%0,%1,%2,%3};"          \
                 : "+f"(d0), "+f"(d1), "+f"(d2), "+f"(d3)                         \
                 : "r"(a0), "r"(a1), "r"(a2), "r"(a3), "r"(b0), "r"(b1))

// ---------------- init ----------------
__global__ void init_state() {
    int idx = blockIdx.x * blockDim.x + threadIdx.x;
    if (idx < Bsz * Hh / 2) ((unsigned*)g_hA)[idx] = 0u;
    if (idx == 0) g_cnt = 0u;
}

// ---------------- precompute x_gates (permuted col layout) ----------------
__global__ void __launch_bounds__(256) xgate_gemm(const float* __restrict__ x,
                                                  const float* __restrict__ Wih,
                                                  const float* __restrict__ bih,
                                                  const float* __restrict__ bhh) {
    __shared__ float A_s[16][64];
    __shared__ float B_s[16][128];
    const int tid = threadIdx.x;
    const int g0 = blockIdx.x * 128;
    const int t0 = blockIdx.y * 64;
    const int b  = blockIdx.z;
    const int ti = tid & 15;
    const int gi = tid >> 4;

    ull acc[4][4];
#pragma unroll
    for (int i = 0; i < 4; i++)
#pragma unroll
        for (int p = 0; p < 4; p++) acc[i][p] = 0ULL;

    const float* xb = x + (size_t)b * Dd * Tt;
    const int stage_row = orig_j(g0 + (tid >> 1));   // fixed per thread
    const int stage_half = tid & 1;

    for (int d0 = 0; d0 < Dd; d0 += 16) {
        __syncthreads();
        {
            int tt = tid & 63, dd = tid >> 6;
#pragma unroll
            for (int r = 0; r < 4; r++)
                A_s[dd + r * 4][tt] = xb[(size_t)(d0 + dd + r * 4) * Tt + t0 + tt];
        }
        {
            int gg = tid >> 1;
            const float* wsrc = Wih + (size_t)stage_row * Dd + d0 + stage_half * 8;
            float4 v0 = *(const float4*)(wsrc);
            float4 v1 = *(const float4*)(wsrc + 4);
            int dd = stage_half * 8;
            B_s[dd + 0][gg] = v0.x; B_s[dd + 1][gg] = v0.y;
            B_s[dd + 2][gg] = v0.z; B_s[dd + 3][gg] = v0.w;
            B_s[dd + 4][gg] = v1.x; B_s[dd + 5][gg] = v1.y;
            B_s[dd + 6][gg] = v1.z; B_s[dd + 7][gg] = v1.w;
        }
        __syncthreads();
#pragma unroll
        for (int dd = 0; dd < 16; dd++) {
            float4 a = *(const float4*)&A_s[dd][ti * 4];
            ull ap0 = pk2(a.x, a.x), ap1 = pk2(a.y, a.y);
            ull ap2 = pk2(a.z, a.z), ap3 = pk2(a.w, a.w);
            const ull* bp = (const ull*)&B_s[dd][gi * 8];
            ull b0 = bp[0], b1 = bp[1], b2 = bp[2], b3 = bp[3];
            acc[0][0] = ffma2(ap0, b0, acc[0][0]); acc[0][1] = ffma2(ap0, b1, acc[0][1]);
            acc[0][2] = ffma2(ap0, b2, acc[0][2]); acc[0][3] = ffma2(ap0, b3, acc[0][3]);
            acc[1][0] = ffma2(ap1, b0, acc[1][0]); acc[1][1] = ffma2(ap1, b1, acc[1][1]);
            acc[1][2] = ffma2(ap1, b2, acc[1][2]); acc[1][3] = ffma2(ap1, b3, acc[1][3]);
            acc[2][0] = ffma2(ap2, b0, acc[2][0]); acc[2][1] = ffma2(ap2, b1, acc[2][1]);
            acc[2][2] = ffma2(ap2, b2, acc[2][2]); acc[2][3] = ffma2(ap2, b3, acc[2][3]);
            acc[3][0] = ffma2(ap3, b0, acc[3][0]); acc[3][1] = ffma2(ap3, b1, acc[3][1]);
            acc[3][2] = ffma2(ap3, b2, acc[3][2]); acc[3][3] = ffma2(ap3, b3, acc[3][3]);
        }
    }

    float bias[8];
#pragma unroll
    for (int j = 0; j < 8; j++) {
        int oj = orig_j(g0 + gi * 8 + j);
        bias[j] = bih[oj] + bhh[oj];
    }

#pragma unroll
    for (int it = 0; it < 4; it++) {
        int tt = t0 + ti * 4 + it;
        float v[8];
#pragma unroll
        for (int p = 0; p < 4; p++) upk2(acc[it][p], v[2 * p], v[2 * p + 1]);
#pragma unroll
        for (int j = 0; j < 8; j++) v[j] += bias[j];
        float* dst = g_xg + ((size_t)tt * Bsz + b) * G4 + g0 + gi * 8;
        *(float4*)(dst)     = make_float4(v[0], v[1], v[2], v[3]);
        *(float4*)(dst + 4) = make_float4(v[4], v[5], v[6], v[7]);
    }
}

// ---------------- persistent HMMA LSTM ----------------
// 128 blocks x 128 threads. block = (m-quarter: 64 batch) x (nt: 16 units -> 64 cols).
// SMEM: A (h) 64 x 512 bf16 (padded 520), restaged per step; B (W) 64 x 512 bf16, once.
// Warp w: rows m0 + w*16 .. +15. Accumulators in registers; c persistent in registers.
__global__ void __launch_bounds__(128, 1) lstm_persist(const float* __restrict__ Whh,
                                                       const float* __restrict__ Wmlp) {
    extern __shared__ __align__(16) __nv_bfloat16 smem[];
    __nv_bfloat16* A_s = smem;                    // [64][PADK]
    __nv_bfloat16* B_s = smem + 64 * PADK;        // [64][PADK]

    const int tid = threadIdx.x;
    const int w = tid >> 5, lane = tid & 31;
    const int mq = blockIdx.x >> 5;               // 0..3
    const int nt = blockIdx.x & 31;               // 0..31
    const int m0 = mq * 64;
    const int n0u = nt * 16;

    // One-time: stage W tile (permuted cols, bf16).
    for (int idx = tid; idx < 64 * 512; idx += 128) {
        int n = idx >> 9, k = idx & 511;
        int a = n >> 5, u = (n & 31) >> 1, e = n & 1;
        int row = (2 * a + e) * Hh + n0u + u;
        B_s[n * PADK + k] = __float2bfloat16(Whh[(size_t)row * Hh + k]);
    }

    const int q = lane >> 2, p = lane & 3;
    const int b1 = m0 + w * 16 + q;               // this thread's two batch rows
    const int b2 = b1 + 8;
    float c1[4], c2[4], wmv[4];
#pragma unroll
    for (int s = 0; s < 4; s++) {
        c1[s] = 0.0f; c2[s] = 0.0f;
        wmv[s] = Wmlp[n0u + 4 * s + p];
    }

    // ldmatrix lane addressing (bytes)
    const uint32_t smA = smem_u32(A_s);
    const uint32_t smB = smem_u32(B_s);
    const uint32_t a_addr0 = smA + (uint32_t)((w * 16 + (lane & 15)) * PADK * 2
                                              + (lane >> 4) * 16);
    const int grp = lane >> 3;
    const uint32_t b_addr0 = smB + (uint32_t)((((grp >> 1) * 8) + (lane & 7)) * PADK * 2
                                              + (grp & 1) * 16);
    __syncthreads();

    for (int t = 0; t < Tt; ++t) {
        const __nv_bfloat16* hprev = (t & 1) ? g_hB : g_hA;
        __nv_bfloat16*       hnext = (t & 1) ? g_hA : g_hB;

        // ---- stage A = h tile (64 x 512 bf16), L2 loads, 16B chunks ----
#pragma unroll
        for (int i = 0; i < 32; ++i) {
            int idx = tid + i * 128;              // 0..4095
            int m = idx >> 6, kc = (idx & 63) << 3;
            uint4 v = __ldcg((const uint4*)(hprev + (size_t)(m0 + m) * Hh + kc));
            *(uint4*)(A_s + m * PADK + kc) = v;
        }
        __syncthreads();

        // ---- K-loop: 32 chunks of 16; 1 A-ldsm + 4 B-ldsm + 8 mma per chunk ----
        float d[8][4];
#pragma unroll
        for (int s = 0; s < 8; s++)
#pragma unroll
            for (int r = 0; r < 4; r++) d[s][r] = 0.0f;

#pragma unroll 4
        for (int kc = 0; kc < 32; ++kc) {
            uint32_t a0, a1, a2, a3;
            LDSM4(a0, a1, a2, a3, a_addr0 + kc * 32);
#pragma unroll
            for (int v = 0; v < 4; ++v) {
                uint32_t r0, r1, r2, r3;
                LDSM4(r0, r1, r2, r3, b_addr0 + (uint32_t)(v * 16 * PADK * 2) + kc * 32);
                MMA16816(d[2 * v][0], d[2 * v][1], d[2 * v][2], d[2 * v][3],
                         a0, a1, a2, a3, r0, r1);
                MMA16816(d[2 * v + 1][0], d[2 * v + 1][1], d[2 * v + 1][2], d[2 * v + 1][3],
                         a0, a1, a2, a3, r2, r3);
            }
        }

        // ---- epilogue: all gates of unit u = 4s+p are in this thread ----
        const float* xb1 = g_xg + ((size_t)t * Bsz + b1) * G4 + nt * 64;
        const float* xb2 = xb1 + (size_t)8 * G4;
        float psum1 = 0.0f, psum2 = 0.0f;
#pragma unroll
        for (int s = 0; s < 4; ++s) {
            int u = 4 * s + p;
            float2 lo1 = __ldcs((const float2*)(xb1 + 2 * u));
            float2 hi1 = __ldcs((const float2*)(xb1 + 32 + 2 * u));
            float2 lo2 = __ldcs((const float2*)(xb2 + 2 * u));
            float2 hi2 = __ldcs((const float2*)(xb2 + 32 + 2 * u));
            {
                float gi = sigf(d[s][0] + lo1.x);
                float gf = sigf(d[s][1] + lo1.y);
                float gg = tanhf_fast(d[s + 4][0] + hi1.x);
                float go = sigf(d[s + 4][1] + hi1.y);
                float cn = gf * c1[s] + gi * gg;
                c1[s] = cn;
                float hn = go * tanhf_fast(cn);
                hnext[(size_t)b1 * Hh + n0u + u] = __float2bfloat16(hn);
                psum1 += hn * wmv[s];
            }
            {
                float gi = sigf(d[s][2] + lo2.x);
                float gf = sigf(d[s][3] + lo2.y);
                float gg = tanhf_fast(d[s + 4][2] + hi2.x);
                float go = sigf(d[s + 4][3] + hi2.y);
                float cn = gf * c2[s] + gi * gg;
                c2[s] = cn;
                float hn = go * tanhf_fast(cn);
                hnext[(size_t)b2 * Hh + n0u + u] = __float2bfloat16(hn);
                psum2 += hn * wmv[s];
            }
        }
        psum1 += __shfl_xor_sync(0xffffffffu, psum1, 1);
        psum1 += __shfl_xor_sync(0xffffffffu, psum1, 2);
        psum2 += __shfl_xor_sync(0xffffffffu, psum2, 1);
        psum2 += __shfl_xor_sync(0xffffffffu, psum2, 2);
        if (p == 0) {
            g_part[((size_t)t * Bsz + b1) * 32 + nt] = psum1;
            g_part[((size_t)t * Bsz + b2) * 32 + nt] = psum2;
        }

        // ---- grid barrier ----
        __threadfence();
        __syncthreads();
        if (tid == 0) {
            unsigned tgt = (unsigned)(t + 1) * NBLK;
            atomicAdd(&g_cnt, 1u);
            while (*((volatile unsigned*)&g_cnt) < tgt) { }
            __threadfence();
        }
        __syncthreads();
    }
}

// ---------------- finalize: sum 32 partials, + b_mlp, sigmoid ----------------
__global__ void finalize(const float* __restrict__ bmlp, float* __restrict__ out) {
    int idx = blockIdx.x * blockDim.x + threadIdx.x;   // t*256 + b
    if (idx >= Tt * Bsz) return;
    int t = idx >> 8, b = idx & 255;
    const float4* pp = (const float4*)(g_part + (size_t)idx * 32);
    float s = bmlp[0];
#pragma unroll
    for (int qq = 0; qq < 8; qq++) {
        float4 v = pp[qq];
        s += (v.x + v.y) + (v.z + v.w);
    }
    out[(size_t)b * Tt + t] = 1.0f / (1.0f + __expf(-s));
}

// ---------------- launch ----------------
extern "C" void kernel_launch(void* const* d_in, const int* in_sizes, int n_in,
                              void* d_out, int out_size) {
    const float* x    = (const float*)d_in[0];
    const float* Wih  = (const float*)d_in[1];
    const float* Whh  = (const float*)d_in[2];
    const float* bih  = (const float*)d_in[3];
    const float* bhh  = (const float*)d_in[4];
    const float* Wmlp = (const float*)d_in[5];
    const float* bmlp = (const float*)d_in[6];
    float* out = (float*)d_out;

    const int smem_bytes = 2 * 64 * PADK * 2;   // 133120
    cudaFuncSetAttribute(lstm_persist, cudaFuncAttributeMaxDynamicSharedMemorySize,
                         smem_bytes);

    init_state<<<512, 256>>>();
    xgate_gemm<<<dim3(G4 / 128, Tt / 64, Bsz), 256>>>(x, Wih, bih, bhh);
    lstm_persist<<<NBLK, 128, smem_bytes>>>(Whh, Wmlp);
    finalize<<<512, 256>>>(bmlp, out);
}

// round 8
// speedup vs baseline: 4.4695x; 1.4520x over previous
#include <cuda_runtime.h>
#include <cuda_bf16.h>
#include <cstdint>

#define Bsz 256
#define Dd  256
#define Tt  512
#define Hh  512
#define G4  2048
#define NBLK 128
#define PADK 520   // recurrence tiles: padded row (bf16 elems)
#define PADD 264   // xgate tiles: padded row for K=256
#define CSTR 72    // xgate output smem stride (floats)

typedef unsigned long long ull;

// ---------------- scratch (device globals; no allocs allowed) ----------------
__device__ float g_xg[(size_t)Tt * Bsz * G4];          // [t][b][P] permuted, bias folded
__device__ __nv_bfloat16 g_xT[(size_t)Bsz * Tt * Dd];  // x transposed+bf16 [b][t][d]
__device__ __nv_bfloat16 g_Wb[G4 * Dd];                // W_ih bf16, permuted rows [P][d]
__device__ float g_bias[G4];                           // b_ih+b_hh permuted
__device__ __nv_bfloat16 g_hA[Bsz * Hh];               // h ping-pong, [b][k] bf16
__device__ __nv_bfloat16 g_hB[Bsz * Hh];
__device__ float g_part[(size_t)Tt * Bsz * 32];        // per-(t,b) partial logits
__device__ unsigned g_cnt;                             // grid barrier counter

// Permutation: storage col P -> original gate-row j = g*512 + U
// P = nt*64 + 32*a + 2*u + e   with  g = 2a+e,  U = nt*16 + u
__device__ __forceinline__ int orig_j(int P) {
    int nt = P >> 6, c = P & 63;
    int a = c >> 5, u = (c & 31) >> 1, e = c & 1;
    return (2 * a + e) * Hh + nt * 16 + u;
}

__device__ __forceinline__ float sigf(float x) { return 1.0f / (1.0f + __expf(-x)); }
__device__ __forceinline__ float tanhf_fast(float x) {
    return 1.0f - 2.0f / (__expf(2.0f * x) + 1.0f);
}
__device__ __forceinline__ uint32_t smem_u32(const void* p) {
    uint32_t a;
    asm("{ .reg .u64 t; cvta.to.shared.u64 t, %1; cvt.u32.u64 %0, t; }" : "=r"(a) : "l"(p));
    return a;
}

#define LDSM4(r0, r1, r2, r3, addr)                                               \
    asm volatile("ldmatrix.sync.aligned.m8n8.x4.shared.b16 {%0,%1,%2,%3}, [%4];"  \
                 : "=r"(r0), "=r"(r1), "=r"(r2), "=r"(r3) : "r"(addr))

#define MMA16816(d0, d1, d2, d3, a0, a1, a2, a3, b0, b1)                          \
    asm volatile("mma.sync.aligned.m16n8k16.row.col.f32.bf16.bf16.f32 "           \
                 "{%0,%1,%2,%3}, {%4,%5,%6,%7}, {%8,%9}, {%0,%1,%2,%3};"          \
                 : "+f"(d0), "+f"(d1), "+f"(d2), "+f"(d3)                         \
                 : "r"(a0), "r"(a1), "r"(a2), "r"(a3), "r"(b0), "r"(b1))

#define CP_ASYNC16(dst, src)                                                      \
    asm volatile("cp.async.cg.shared.global [%0], [%1], 16;" :: "r"(dst), "l"(src))
#define CP_COMMIT()  asm volatile("cp.async.commit_group;")
#define CP_WAIT(n)   asm volatile("cp.async.wait_group %0;" :: "n"(n))

// ---------------- init ----------------
__global__ void init_state() {
    int idx = blockIdx.x * blockDim.x + threadIdx.x;
    if (idx < Bsz * Hh / 2) ((unsigned*)g_hA)[idx] = 0u;
    if (idx == 0) g_cnt = 0u;
}

// ---------------- convert x: [b][d][t] fp32 -> [b][t][d] bf16 ----------------
__global__ void __launch_bounds__(256) convert_x(const float* __restrict__ x) {
    __shared__ float tile[32][33];
    const int t0 = blockIdx.x * 32;
    const int d0 = blockIdx.y * 32;
    const int b  = blockIdx.z;
    const int tx = threadIdx.x & 31, ty = threadIdx.x >> 5;   // 32 x 8
    const float* xb = x + (size_t)b * Dd * Tt;
#pragma unroll
    for (int r = 0; r < 4; r++)
        tile[ty + r * 8][tx] = xb[(size_t)(d0 + ty + r * 8) * Tt + t0 + tx];
    __syncthreads();
    __nv_bfloat16* dst = g_xT + (size_t)b * Tt * Dd;
#pragma unroll
    for (int r = 0; r < 4; r++)
        dst[(size_t)(t0 + ty + r * 8) * Dd + d0 + tx] = __float2bfloat16(tile[tx][ty + r * 8]);
}

// ---------------- convert W_ih (permuted rows) + bias ----------------
__global__ void __launch_bounds__(256) convert_w(const float* __restrict__ Wih,
                                                 const float* __restrict__ bih,
                                                 const float* __restrict__ bhh) {
    int idx = blockIdx.x * blockDim.x + threadIdx.x;     // 524288 threads
    if (idx < G4 * Dd) {
        int P = idx >> 8, d = idx & 255;
        g_Wb[idx] = __float2bfloat16(Wih[(size_t)orig_j(P) * Dd + d]);
    }
    if (idx < G4) {
        int oj = orig_j(idx);
        g_bias[idx] = bih[oj] + bhh[oj];
    }
}

// ---------------- xgate GEMM (bf16 HMMA): per b, (T x D) @ (D x P) ----------------
// grid (32 P-tiles, 8 t-tiles, 256 b), 128 threads. Tile M=64,N=64,K=256.
__global__ void __launch_bounds__(128) xgate_mma(int dummy) {
    extern __shared__ __align__(16) __nv_bfloat16 smem[];
    __nv_bfloat16* A_s = smem;                    // [64][PADD]  (overlaid by C_s later)
    __nv_bfloat16* B_s = smem + 64 * PADD;        // [64][PADD]
    float* C_s   = (float*)smem;                  // [64][CSTR]
    float* bias_s = (float*)(smem + 2 * 64 * PADD);  // [64]

    const int tid = threadIdx.x;
    const int w = tid >> 5, lane = tid & 31;
    const int P0 = blockIdx.x * 64;
    const int t0 = blockIdx.y * 64;
    const int b  = blockIdx.z;

    if (tid < 64) bias_s[tid] = g_bias[P0 + tid];

    // stage A (x rows) and B (W rows)
    {
        const __nv_bfloat16* asrc = g_xT + ((size_t)b * Tt + t0) * Dd;
#pragma unroll
        for (int i = 0; i < 16; ++i) {
            int idx = tid + i * 128;
            int m = idx >> 5, k8 = (idx & 31) << 3;
            *(uint4*)(A_s + m * PADD + k8) = *(const uint4*)(asrc + (size_t)m * Dd + k8);
        }
        const __nv_bfloat16* bsrc = g_Wb + (size_t)P0 * Dd;
#pragma unroll
        for (int i = 0; i < 16; ++i) {
            int idx = tid + i * 128;
            int n = idx >> 5, k8 = (idx & 31) << 3;
            *(uint4*)(B_s + n * PADD + k8) = *(const uint4*)(bsrc + (size_t)n * Dd + k8);
        }
    }
    __syncthreads();

    const uint32_t smA = smem_u32(A_s);
    const uint32_t smB = smem_u32(B_s);
    const uint32_t a_addr0 = smA + (uint32_t)((w * 16 + (lane & 15)) * PADD * 2
                                              + (lane >> 4) * 16);
    const int grp = lane >> 3;
    const uint32_t b_addr0 = smB + (uint32_t)((((grp >> 1) * 8) + (lane & 7)) * PADD * 2
                                              + (grp & 1) * 16);

    float d[8][4];
#pragma unroll
    for (int s = 0; s < 8; s++)
#pragma unroll
        for (int r = 0; r < 4; r++) d[s][r] = 0.0f;

#pragma unroll 4
    for (int kc = 0; kc < 16; ++kc) {
        uint32_t a0, a1, a2, a3;
        LDSM4(a0, a1, a2, a3, a_addr0 + kc * 32);
#pragma unroll
        for (int v = 0; v < 4; ++v) {
            uint32_t r0, r1, r2, r3;
            LDSM4(r0, r1, r2, r3, b_addr0 + (uint32_t)(v * 16 * PADD * 2) + kc * 32);
            MMA16816(d[2 * v][0], d[2 * v][1], d[2 * v][2], d[2 * v][3],
                     a0, a1, a2, a3, r0, r1);
            MMA16816(d[2 * v + 1][0], d[2 * v + 1][1], d[2 * v + 1][2], d[2 * v + 1][3],
                     a0, a1, a2, a3, r2, r3);
        }
    }
    __syncthreads();   // done reading A_s; reuse as C_s

    // dump fragments: thread (q,p) rows w*16+q(+8), cols 16v+8e+2p,+1
    const int q = lane >> 2, p = lane & 3;
#pragma unroll
    for (int v = 0; v < 4; ++v)
#pragma unroll
        for (int e = 0; e < 2; ++e) {
            int j = 2 * v + e, c = 16 * v + 8 * e + 2 * p;
            *(float2*)(C_s + (w * 16 + q) * CSTR + c)     = make_float2(d[j][0], d[j][1]);
            *(float2*)(C_s + (w * 16 + q + 8) * CSTR + c) = make_float2(d[j][2], d[j][3]);
        }
    __syncthreads();

    // coalesced copy-out with bias
    {
        int r = tid >> 1, half = tid & 1, c0 = half * 32;
        float* dst = g_xg + ((size_t)(t0 + r) * Bsz + b) * G4 + P0 + c0;
        const float* src = C_s + r * CSTR + c0;
#pragma unroll
        for (int qq = 0; qq < 8; ++qq) {
            float4 v = *(const float4*)(src + 4 * qq);
            v.x += bias_s[c0 + 4 * qq + 0];
            v.y += bias_s[c0 + 4 * qq + 1];
            v.z += bias_s[c0 + 4 * qq + 2];
            v.w += bias_s[c0 + 4 * qq + 3];
            *(float4*)(dst + 4 * qq) = v;
        }
    }
}

// ---------------- persistent HMMA LSTM ----------------
// 128 blocks x 128 threads. block = (m-quarter: 64 batch) x (nt: 16 units -> 64 cols).
// cp.async two-half pipelined A staging; x_gates prefetched one step ahead.
__global__ void __launch_bounds__(128, 1) lstm_persist(const float* __restrict__ Whh,
                                                       const float* __restrict__ Wmlp) {
    extern __shared__ __align__(16) __nv_bfloat16 smem[];
    __nv_bfloat16* A_s = smem;                    // [64][PADK]
    __nv_bfloat16* B_s = smem + 64 * PADK;        // [64][PADK]

    const int tid = threadIdx.x;
    const int w = tid >> 5, lane = tid & 31;
    const int mq = blockIdx.x >> 5;               // 0..3
    const int nt = blockIdx.x & 31;               // 0..31
    const int m0 = mq * 64;
    const int n0u = nt * 16;

    // One-time: stage W tile (permuted cols, bf16).
    for (int idx = tid; idx < 64 * 512; idx += 128) {
        int n = idx >> 9, k = idx & 511;
        int a = n >> 5, u = (n & 31) >> 1, e = n & 1;
        int row = (2 * a + e) * Hh + n0u + u;
        B_s[n * PADK + k] = __float2bfloat16(Whh[(size_t)row * Hh + k]);
    }

    const int q = lane >> 2, p = lane & 3;
    const int b1 = m0 + w * 16 + q;
    const int b2 = b1 + 8;
    float c1[4], c2[4], wmv[4];
#pragma unroll
    for (int s = 0; s < 4; s++) {
        c1[s] = 0.0f; c2[s] = 0.0f;
        wmv[s] = Wmlp[n0u + 4 * s + p];
    }

    const uint32_t smA = smem_u32(A_s);
    const uint32_t smB = smem_u32(B_s);
    const uint32_t a_addr0 = smA + (uint32_t)((w * 16 + (lane & 15)) * PADK * 2
                                              + (lane >> 4) * 16);
    const int grp = lane >> 3;
    const uint32_t b_addr0 = smB + (uint32_t)((((grp >> 1) * 8) + (lane & 7)) * PADK * 2
                                              + (grp & 1) * 16);

    // x prefetch registers: [lo/hi][b1/b2][s]
    float2 xr[2][2][4];
    {
        const float* xb1 = g_xg + ((size_t)0 * Bsz + b1) * G4 + nt * 64;
        const float* xb2 = xb1 + (size_t)(b2 - b1) * G4;
#pragma unroll
        for (int s = 0; s < 4; ++s) {
            int u = 4 * s + p;
            xr[0][0][s] = __ldcs((const float2*)(xb1 + 2 * u));
            xr[1][0][s] = __ldcs((const float2*)(xb1 + 32 + 2 * u));
            xr[0][1][s] = __ldcs((const float2*)(xb2 + 2 * u));
            xr[1][1][s] = __ldcs((const float2*)(xb2 + 32 + 2 * u));
        }
    }
    __syncthreads();

    for (int t = 0; t < Tt; ++t) {
        const __nv_bfloat16* hprev = (t & 1) ? g_hB : g_hA;
        __nv_bfloat16*       hnext = (t & 1) ? g_hA : g_hB;

        // ---- stage A via cp.async, two K-halves ----
#pragma unroll
        for (int i = 0; i < 16; ++i) {
            int idx = tid + i * 128;
            int m = idx >> 5, k8 = (idx & 31) << 3;      // k 0..255
            CP_ASYNC16(smA + (uint32_t)(m * PADK + k8) * 2,
                       hprev + (size_t)(m0 + m) * Hh + k8);
        }
        CP_COMMIT();
#pragma unroll
        for (int i = 0; i < 16; ++i) {
            int idx = tid + i * 128;
            int m = idx >> 5, k8 = ((idx & 31) << 3) + 256;  // k 256..511
            CP_ASYNC16(smA + (uint32_t)(m * PADK + k8) * 2,
                       hprev + (size_t)(m0 + m) * Hh + k8);
        }
        CP_COMMIT();

        float d[8][4];
#pragma unroll
        for (int s = 0; s < 8; s++)
#pragma unroll
            for (int r = 0; r < 4; r++) d[s][r] = 0.0f;

        CP_WAIT(1);
        __syncthreads();
#pragma unroll 4
        for (int kc = 0; kc < 16; ++kc) {
            uint32_t a0, a1, a2, a3;
            LDSM4(a0, a1, a2, a3, a_addr0 + kc * 32);
#pragma unroll
            for (int v = 0; v < 4; ++v) {
                uint32_t r0, r1, r2, r3;
                LDSM4(r0, r1, r2, r3, b_addr0 + (uint32_t)(v * 16 * PADK * 2) + kc * 32);
                MMA16816(d[2 * v][0], d[2 * v][1], d[2 * v][2], d[2 * v][3],
                         a0, a1, a2, a3, r0, r1);
                MMA16816(d[2 * v + 1][0], d[2 * v + 1][1], d[2 * v + 1][2], d[2 * v + 1][3],
                         a0, a1, a2, a3, r2, r3);
            }
        }
        CP_WAIT(0);
        __syncthreads();
#pragma unroll 4
        for (int kc = 16; kc < 32; ++kc) {
            uint32_t a0, a1, a2, a3;
            LDSM4(a0, a1, a2, a3, a_addr0 + kc * 32);
#pragma unroll
            for (int v = 0; v < 4; ++v) {
                uint32_t r0, r1, r2, r3;
                LDSM4(r0, r1, r2, r3, b_addr0 + (uint32_t)(v * 16 * PADK * 2) + kc * 32);
                MMA16816(d[2 * v][0], d[2 * v][1], d[2 * v][2], d[2 * v][3],
                         a0, a1, a2, a3, r0, r1);
                MMA16816(d[2 * v + 1][0], d[2 * v + 1][1], d[2 * v + 1][2], d[2 * v + 1][3],
                         a0, a1, a2, a3, r2, r3);
            }
        }

        // ---- epilogue (x already in registers) ----
        float psum1 = 0.0f, psum2 = 0.0f;
#pragma unroll
        for (int s = 0; s < 4; ++s) {
            int u = 4 * s + p;
            {
                float gi = sigf(d[s][0] + xr[0][0][s].x);
                float gf = sigf(d[s][1] + xr[0][0][s].y);
                float gg = tanhf_fast(d[s + 4][0] + xr[1][0][s].x);
                float go = sigf(d[s + 4][1] + xr[1][0][s].y);
                float cn = gf * c1[s] + gi * gg;
                c1[s] = cn;
                float hn = go * tanhf_fast(cn);
                hnext[(size_t)b1 * Hh + n0u + u] = __float2bfloat16(hn);
                psum1 += hn * wmv[s];
            }
            {
                float gi = sigf(d[s][2] + xr[0][1][s].x);
                float gf = sigf(d[s][3] + xr[0][1][s].y);
                float gg = tanhf_fast(d[s + 4][2] + xr[1][1][s].x);
                float go = sigf(d[s + 4][3] + xr[1][1][s].y);
                float cn = gf * c2[s] + gi * gg;
                c2[s] = cn;
                float hn = go * tanhf_fast(cn);
                hnext[(size_t)b2 * Hh + n0u + u] = __float2bfloat16(hn);
                psum2 += hn * wmv[s];
            }
        }
        psum1 += __shfl_xor_sync(0xffffffffu, psum1, 1);
        psum1 += __shfl_xor_sync(0xffffffffu, psum1, 2);
        psum2 += __shfl_xor_sync(0xffffffffu, psum2, 1);
        psum2 += __shfl_xor_sync(0xffffffffu, psum2, 2);
        if (p == 0) {
            g_part[((size_t)t * Bsz + b1) * 32 + nt] = psum1;
            g_part[((size_t)t * Bsz + b2) * 32 + nt] = psum2;
        }

        // ---- make h visible, then prefetch next x under the barrier ----
        __threadfence();
        __syncthreads();
        {
            int tp = (t + 1 < Tt) ? t + 1 : t;
            const float* xb1 = g_xg + ((size_t)tp * Bsz + b1) * G4 + nt * 64;
            const float* xb2 = xb1 + (size_t)(b2 - b1) * G4;
#pragma unroll
            for (int s = 0; s < 4; ++s) {
                int u = 4 * s + p;
                xr[0][0][s] = __ldcs((const float2*)(xb1 + 2 * u));
                xr[1][0][s] = __ldcs((const float2*)(xb1 + 32 + 2 * u));
                xr[0][1][s] = __ldcs((const float2*)(xb2 + 2 * u));
                xr[1][1][s] = __ldcs((const float2*)(xb2 + 32 + 2 * u));
            }
        }
        if (tid == 0) {
            unsigned tgt = (unsigned)(t + 1) * NBLK;
            atomicAdd(&g_cnt, 1u);
            while (*((volatile unsigned*)&g_cnt) < tgt) { }
            __threadfence();
        }
        __syncthreads();
    }
}

// ---------------- finalize: sum 32 partials, + b_mlp, sigmoid ----------------
__global__ void finalize(const float* __restrict__ bmlp, float* __restrict__ out) {
    int idx = blockIdx.x * blockDim.x + threadIdx.x;   // t*256 + b
    if (idx >= Tt * Bsz) return;
    int t = idx >> 8, b = idx & 255;
    const float4* pp = (const float4*)(g_part + (size_t)idx * 32);
    float s = bmlp[0];
#pragma unroll
    for (int qq = 0; qq < 8; qq++) {
        float4 v = pp[qq];
        s += (v.x + v.y) + (v.z + v.w);
    }
    out[(size_t)b * Tt + t] = 1.0f / (1.0f + __expf(-s));
}

// ---------------- launch ----------------
extern "C" void kernel_launch(void* const* d_in, const int* in_sizes, int n_in,
                              void* d_out, int out_size) {
    const float* x    = (const float*)d_in[0];
    const float* Wih  = (const float*)d_in[1];
    const float* Whh  = (const float*)d_in[2];
    const float* bih  = (const float*)d_in[3];
    const float* bhh  = (const float*)d_in[4];
    const float* Wmlp = (const float*)d_in[5];
    const float* bmlp = (const float*)d_in[6];
    float* out = (float*)d_out;

    const int smem_lstm  = 2 * 64 * PADK * 2;                 // 133120
    const int smem_xgate = 2 * 64 * PADD * 2 + 64 * 4;        // 67840
    cudaFuncSetAttribute(lstm_persist, cudaFuncAttributeMaxDynamicSharedMemorySize,
                         smem_lstm);
    cudaFuncSetAttribute(xgate_mma, cudaFuncAttributeMaxDynamicSharedMemorySize,
                         smem_xgate);

    init_state<<<512, 256>>>();
    convert_x<<<dim3(Tt / 32, Dd / 32, Bsz), 256>>>(x);
    convert_w<<<G4 * Dd / 256, 256>>>(Wih, bih, bhh);
    xgate_mma<<<dim3(G4 / 64, Tt / 64, Bsz), 128, smem_xgate>>>(0);
    lstm_persist<<<NBLK, 128, smem_lstm>>>(Whh, Wmlp);
    finalize<<<512, 256>>>(bmlp, out);
}